// round 16
// baseline (speedup 1.0000x reference)
#include <cuda_runtime.h>
#include <cuda_bf16.h>

#define N_NODES 100000
#define N_EDGES 1600000
#define F       64
#define N_GRAPHS 1024
#define BIO     2048

#define SCAN_NB   400          // 400 blocks * 256 = 102400 >= N_NODES

// ---------------- scratch (static device globals; no allocation) -------------
__device__ float g_A[N_NODES * F];      // hw  (GEMM output, gather source)
__device__ float g_B[N_NODES * F];      // h   (layer output / gemm input)
__device__ float g_dinv[N_NODES];
__device__ int   g_deg[N_NODES];
__device__ int   g_off[N_NODES + 1];
__device__ int   g_cur[N_NODES];
__device__ int   g_bsum[SCAN_NB];
__device__ int   g_bscan[SCAN_NB];
__device__ int   g_csrc[N_EDGES];       // src node per CSR slot (sorted by dst)
__device__ float g_cw[N_EDGES];         // dinv[src] per CSR slot
__device__ float g_pooled[N_GRAPHS * F];

// ---------------- degree histogram + dinv ------------------------------------
__global__ void k_zero_deg() {
    int i = blockIdx.x * blockDim.x + threadIdx.x;
    if (i < N_NODES) g_deg[i] = 0;
}

__global__ void k_hist(const int* __restrict__ ei) {
    int e = blockIdx.x * blockDim.x + threadIdx.x;
    if (e < N_EDGES) {
        int d = ei[N_EDGES + e];
        if (d >= 0 && d < N_NODES) atomicAdd(&g_deg[d], 1);
    }
}

__global__ void k_dinv() {
    int i = blockIdx.x * blockDim.x + threadIdx.x;
    if (i < N_NODES) g_dinv[i] = rsqrtf((float)g_deg[i] + 1.0f);
}

// ---------------- phase 1: per-block sums of 256 degrees ----------------------
__global__ void k_scan_partial() {
    __shared__ int sm[256];
    int t = threadIdx.x;
    int i = blockIdx.x * 256 + t;
    int v = (i < N_NODES) ? g_deg[i] : 0;
    sm[t] = v;
    __syncthreads();
    for (int s = 128; s > 0; s >>= 1) {
        if (t < s) sm[t] += sm[t + s];
        __syncthreads();
    }
    if (t == 0) g_bsum[blockIdx.x] = sm[0];
}

// ---------------- phase 2: one block scans SCAN_NB block sums -----------------
__global__ void k_scan_blocks() {
    __shared__ int sm[512];
    int t = threadIdx.x;                       // 512 threads
    int v = (t < SCAN_NB) ? g_bsum[t] : 0;
    sm[t] = v;
    __syncthreads();
    for (int d = 1; d < 512; d <<= 1) {
        int u = (t >= d) ? sm[t - d] : 0;
        __syncthreads();
        sm[t] += u;
        __syncthreads();
    }
    if (t < SCAN_NB) g_bscan[t] = sm[t] - v;   // exclusive
    if (t == SCAN_NB - 1) g_off[N_NODES] = sm[t];
}

// ---------------- phase 3: block-local scan + base → offsets ------------------
__global__ void k_scan_offsets() {
    __shared__ int sm[256];
    int t = threadIdx.x;
    int i = blockIdx.x * 256 + t;
    int v = (i < N_NODES) ? g_deg[i] : 0;
    sm[t] = v;
    __syncthreads();
    for (int d = 1; d < 256; d <<= 1) {
        int u = (t >= d) ? sm[t - d] : 0;
        __syncthreads();
        sm[t] += u;
        __syncthreads();
    }
    if (i < N_NODES) {
        int off = g_bscan[blockIdx.x] + sm[t] - v;   // exclusive within block
        g_off[i] = off;
        g_cur[i] = off;
    }
}

// ---------------- CSR fill ----------------------------------------------------
__global__ void k_fill(const int* __restrict__ ei) {
    int e = blockIdx.x * blockDim.x + threadIdx.x;
    if (e < N_EDGES) {
        int s = ei[e];
        int d = ei[N_EDGES + e];
        if (s >= 0 && s < N_NODES && d >= 0 && d < N_NODES) {
            int pos = atomicAdd(&g_cur[d], 1);
            g_csrc[pos] = s;
            g_cw[pos]   = g_dinv[s];
        }
    }
}

// ---------------- GEMM core: 32 rows/block, 256 threads ----------------------
__device__ __forceinline__ void gemm_body(const float* __restrict__ in,
                                          const float* __restrict__ W,
                                          float* __restrict__ out) {
    __shared__ float Ws[64 * 64];
    __shared__ float Hs[32 * 64];
    int tid  = threadIdx.x;
    int row0 = blockIdx.x * 32;

    #pragma unroll
    for (int j = 0; j < 16; j++) Ws[tid + j * 256] = W[tid + j * 256];
    #pragma unroll
    for (int j = 0; j < 8; j++)
        Hs[tid + j * 256] = in[(size_t)row0 * 64 + tid + j * 256];
    __syncthreads();

    int r  = tid >> 3;          // 0..31
    int c0 = (tid & 7) * 8;     // 0,8,...,56
    float acc[8];
    #pragma unroll
    for (int j = 0; j < 8; j++) acc[j] = 0.0f;

    #pragma unroll
    for (int k = 0; k < 64; k++) {
        float a = Hs[r * 64 + k];
        float4 w0 = *(const float4*)&Ws[k * 64 + c0];
        float4 w1 = *(const float4*)&Ws[k * 64 + c0 + 4];
        acc[0] += a * w0.x; acc[1] += a * w0.y; acc[2] += a * w0.z; acc[3] += a * w0.w;
        acc[4] += a * w1.x; acc[5] += a * w1.y; acc[6] += a * w1.z; acc[7] += a * w1.w;
    }
    float* dst = out + (size_t)(row0 + r) * 64 + c0;
    *(float4*)dst       = make_float4(acc[0], acc[1], acc[2], acc[3]);
    *(float4*)(dst + 4) = make_float4(acc[4], acc[5], acc[6], acc[7]);
}

// layer 1: read external input x, write g_A
__global__ void k_gemm_x(const float* __restrict__ x, const float* __restrict__ W) {
    gemm_body(x, W, g_A);
}
// layers 2/3: read g_B, write g_A
__global__ void k_gemm_B(const float* __restrict__ W) {
    gemm_body(g_B, W, g_A);
}

// ---------------- aggregation: 2 nodes per warp, float4 per lane --------------
// reads g_A, writes g_B.  (idempotent — launched twice for timing attribution)
__global__ void k_agg(const float* __restrict__ b, int do_relu) {
    int gtid = blockIdx.x * blockDim.x + threadIdx.x;
    int warp = gtid >> 5;
    int lane = threadIdx.x & 31;
    int node = warp * 2 + (lane >> 4);      // half-warp per node
    int sub  = lane & 15;
    if (node >= N_NODES) return;
    const float* __restrict__ hw = g_A;
    int f = sub * 4;

    float dv = g_dinv[node];
    int lo = g_off[node];
    int hi = g_off[node + 1];

    float4 acc = make_float4(0.f, 0.f, 0.f, 0.f);
    int e = lo;
    for (; e + 1 < hi; e += 2) {
        int   s0 = g_csrc[e];     int   s1 = g_csrc[e + 1];
        float w0 = g_cw[e];       float w1 = g_cw[e + 1];
        float4 v0 = *(const float4*)&hw[(size_t)s0 * 64 + f];
        float4 v1 = *(const float4*)&hw[(size_t)s1 * 64 + f];
        acc.x += w0 * v0.x + w1 * v1.x;
        acc.y += w0 * v0.y + w1 * v1.y;
        acc.z += w0 * v0.z + w1 * v1.z;
        acc.w += w0 * v0.w + w1 * v1.w;
    }
    if (e < hi) {
        int   s0 = g_csrc[e];
        float w0 = g_cw[e];
        float4 v0 = *(const float4*)&hw[(size_t)s0 * 64 + f];
        acc.x += w0 * v0.x;
        acc.y += w0 * v0.y;
        acc.z += w0 * v0.z;
        acc.w += w0 * v0.w;
    }

    float4 self = *(const float4*)&hw[(size_t)node * 64 + f];
    float4 bb   = *(const float4*)&b[f];
    float dv2 = dv * dv;
    float ox = dv * acc.x + dv2 * self.x + bb.x;
    float oy = dv * acc.y + dv2 * self.y + bb.y;
    float oz = dv * acc.z + dv2 * self.z + bb.z;
    float ow = dv * acc.w + dv2 * self.w + bb.w;
    if (do_relu) {
        ox = fmaxf(ox, 0.f); oy = fmaxf(oy, 0.f);
        oz = fmaxf(oz, 0.f); ow = fmaxf(ow, 0.f);
    }
    *(float4*)&g_B[(size_t)node * 64 + f] = make_float4(ox, oy, oz, ow);
}

// ---------------- pool: one block (64 threads) per graph ----------------------
__device__ __forceinline__ int lb_i32(const int* a, int n, int key) {
    int lo = 0, hi = n;
    while (lo < hi) {
        int mid = (lo + hi) >> 1;
        if (a[mid] < key) lo = mid + 1; else hi = mid;
    }
    return lo;
}

__global__ void k_pool(const int* __restrict__ batch) {
    int g = blockIdx.x;
    int f = threadIdx.x;   // 0..63
    int lo = lb_i32(batch, N_NODES, g);
    int hi = lb_i32(batch, N_NODES, g + 1);
    float s = 0.f;
    for (int n = lo; n < hi; n++) s += g_B[(size_t)n * 64 + f];
    int cnt = hi - lo;
    float denom = (float)max(cnt, 1);
    g_pooled[g * 64 + f] = s / denom;
}

// ---------------- dense + softmax + threshold: one block per graph ------------
__global__ void k_dense(const float* __restrict__ Wd,
                        const float* __restrict__ bd,
                        float* __restrict__ out) {
    __shared__ float p[64];
    __shared__ float red[256];
    int g = blockIdx.x;
    int tid = threadIdx.x;  // 256 threads
    if (tid < 64) p[tid] = g_pooled[g * 64 + tid];
    __syncthreads();

    float l[8];
    #pragma unroll
    for (int j = 0; j < 8; j++) l[j] = bd[tid + j * 256];
    for (int k = 0; k < 64; k++) {
        float pk = p[k];
        const float* wrow = Wd + (size_t)k * BIO;
        #pragma unroll
        for (int j = 0; j < 8; j++) l[j] += pk * wrow[tid + j * 256];
    }

    // block max
    float mx = l[0];
    #pragma unroll
    for (int j = 1; j < 8; j++) mx = fmaxf(mx, l[j]);
    red[tid] = mx;
    __syncthreads();
    for (int s = 128; s > 0; s >>= 1) {
        if (tid < s) red[tid] = fmaxf(red[tid], red[tid + s]);
        __syncthreads();
    }
    mx = red[0];
    __syncthreads();

    // block sum of exp
    float se = 0.f;
    float ex[8];
    #pragma unroll
    for (int j = 0; j < 8; j++) { ex[j] = expf(l[j] - mx); se += ex[j]; }
    red[tid] = se;
    __syncthreads();
    for (int s = 128; s > 0; s >>= 1) {
        if (tid < s) red[tid] += red[tid + s];
        __syncthreads();
    }
    float total = red[0];

    #pragma unroll
    for (int j = 0; j < 8; j++)
        out[(size_t)g * BIO + tid + j * 256] = (ex[j] >= 0.5f * total) ? 1.0f : 0.0f;
}

// ---------------- launch ------------------------------------------------------
extern "C" void kernel_launch(void* const* d_in, const int* in_sizes, int n_in,
                              void* d_out, int out_size) {
    // Identify inputs by element count (robust to metadata ordering).
    const float *x = 0, *W1 = 0, *b1 = 0, *W2 = 0, *b2 = 0, *W3 = 0, *b3 = 0,
                *Wd = 0, *bd = 0;
    const int *ei = 0, *batch = 0;
    int nW = 0, nb = 0;
    for (int i = 0; i < n_in; i++) {
        int sz = in_sizes[i];
        if      (sz == N_NODES * F)   x     = (const float*)d_in[i];
        else if (sz == 2 * N_EDGES)   ei    = (const int*)d_in[i];
        else if (sz == N_NODES)       batch = (const int*)d_in[i];
        else if (sz == F * F) {
            if      (nW == 0) W1 = (const float*)d_in[i];
            else if (nW == 1) W2 = (const float*)d_in[i];
            else              W3 = (const float*)d_in[i];
            nW++;
        }
        else if (sz == F) {
            if      (nb == 0) b1 = (const float*)d_in[i];
            else if (nb == 1) b2 = (const float*)d_in[i];
            else              b3 = (const float*)d_in[i];
            nb++;
        }
        else if (sz == F * BIO)       Wd = (const float*)d_in[i];
        else if (sz == BIO)           bd = (const float*)d_in[i];
    }
    float* out = (float*)d_out;

    k_zero_deg<<<(N_NODES + 255) / 256, 256>>>();
    k_hist<<<(N_EDGES + 255) / 256, 256>>>(ei);
    k_dinv<<<(N_NODES + 255) / 256, 256>>>();
    k_scan_partial<<<SCAN_NB, 256>>>();
    k_scan_blocks<<<1, 512>>>();
    k_scan_offsets<<<SCAN_NB, 256>>>();
    k_fill<<<(N_EDGES + 255) / 256, 256>>>(ei);

    // layer 1  — agg launched TWICE (idempotent) to expose T_agg in total time
    k_gemm_x<<<N_NODES / 32, 256>>>(x, W1);
    k_agg<<<6250, 256>>>(b1, 1);
    k_agg<<<6250, 256>>>(b1, 1);
    // layer 2
    k_gemm_B<<<N_NODES / 32, 256>>>(W2);
    k_agg<<<6250, 256>>>(b2, 1);
    k_agg<<<6250, 256>>>(b2, 1);
    // layer 3
    k_gemm_B<<<N_NODES / 32, 256>>>(W3);
    k_agg<<<6250, 256>>>(b3, 0);
    k_agg<<<6250, 256>>>(b3, 0);

    k_pool<<<N_GRAPHS, 64>>>(batch);
    k_dense<<<N_GRAPHS, 256>>>(Wd, bd, out);
}

// round 17
// speedup vs baseline: 2.0434x; 2.0434x over previous
#include <cuda_runtime.h>
#include <cuda_bf16.h>

#define N_NODES 100000
#define N_EDGES 1600000
#define F       64
#define N_GRAPHS 1024
#define BIO     2048

#define SCAN_NB   400          // 400 blocks * 256 = 102400 >= N_NODES
#define GEMM_NB   782          // 782 * 128 = 100096 >= N_NODES

// ---------------- scratch (static device globals; no allocation) -------------
__device__ float g_A[N_NODES * F];      // hw  (GEMM output, gather source)
__device__ float g_B[N_NODES * F];      // h   (layer output / gemm input)
__device__ float g_dinv[N_NODES];
__device__ int   g_deg[N_NODES];
__device__ int   g_off[N_NODES + 1];
__device__ int   g_cur[N_NODES];
__device__ int   g_bsum[SCAN_NB];
__device__ int   g_bscan[SCAN_NB];
__device__ int2  g_edge[N_EDGES];       // {src, bitcast(dinv[src])} per CSR slot
__device__ float g_pooled[N_GRAPHS * F];

// ---------------- degree histogram + dinv ------------------------------------
__global__ void k_zero_deg() {
    int i = blockIdx.x * blockDim.x + threadIdx.x;
    if (i < N_NODES) g_deg[i] = 0;
}

__global__ void k_hist(const int* __restrict__ ei) {
    int e = blockIdx.x * blockDim.x + threadIdx.x;
    if (e < N_EDGES) {
        int d = ei[N_EDGES + e];
        if (d >= 0 && d < N_NODES) atomicAdd(&g_deg[d], 1);
    }
}

__global__ void k_dinv() {
    int i = blockIdx.x * blockDim.x + threadIdx.x;
    if (i < N_NODES) g_dinv[i] = rsqrtf((float)g_deg[i] + 1.0f);
}

// ---------------- phase 1: per-block sums of 256 degrees ----------------------
__global__ void k_scan_partial() {
    __shared__ int sm[256];
    int t = threadIdx.x;
    int i = blockIdx.x * 256 + t;
    int v = (i < N_NODES) ? g_deg[i] : 0;
    sm[t] = v;
    __syncthreads();
    for (int s = 128; s > 0; s >>= 1) {
        if (t < s) sm[t] += sm[t + s];
        __syncthreads();
    }
    if (t == 0) g_bsum[blockIdx.x] = sm[0];
}

// ---------------- phase 2: one block scans SCAN_NB block sums -----------------
__global__ void k_scan_blocks() {
    __shared__ int sm[512];
    int t = threadIdx.x;                       // 512 threads
    int v = (t < SCAN_NB) ? g_bsum[t] : 0;
    sm[t] = v;
    __syncthreads();
    for (int d = 1; d < 512; d <<= 1) {
        int u = (t >= d) ? sm[t - d] : 0;
        __syncthreads();
        sm[t] += u;
        __syncthreads();
    }
    if (t < SCAN_NB) g_bscan[t] = sm[t] - v;   // exclusive
    if (t == SCAN_NB - 1) g_off[N_NODES] = sm[t];
}

// ---------------- phase 3: block-local scan + base → offsets ------------------
__global__ void k_scan_offsets() {
    __shared__ int sm[256];
    int t = threadIdx.x;
    int i = blockIdx.x * 256 + t;
    int v = (i < N_NODES) ? g_deg[i] : 0;
    sm[t] = v;
    __syncthreads();
    for (int d = 1; d < 256; d <<= 1) {
        int u = (t >= d) ? sm[t - d] : 0;
        __syncthreads();
        sm[t] += u;
        __syncthreads();
    }
    if (i < N_NODES) {
        int off = g_bscan[blockIdx.x] + sm[t] - v;   // exclusive within block
        g_off[i] = off;
        g_cur[i] = off;
    }
}

// ---------------- CSR fill: single 8B scatter per edge ------------------------
__global__ void k_fill(const int* __restrict__ ei) {
    int e = blockIdx.x * blockDim.x + threadIdx.x;
    if (e < N_EDGES) {
        int s = ei[e];
        int d = ei[N_EDGES + e];
        if (s >= 0 && s < N_NODES && d >= 0 && d < N_NODES) {
            int pos = atomicAdd(&g_cur[d], 1);
            g_edge[pos] = make_int2(s, __float_as_int(g_dinv[s]));
        }
    }
}

// ---------------- GEMM: 128 rows/block, 4 rows/thread, FMA-bound --------------
__device__ __forceinline__ void gemm_body(const float* __restrict__ in,
                                          const float* __restrict__ W,
                                          float* __restrict__ out) {
    __shared__ float Ws[64 * 64];
    __shared__ float Hs[128 * 65];       // stride 65: conflict-free a-loads
    int tid  = threadIdx.x;
    int row0 = blockIdx.x * 128;

    #pragma unroll
    for (int j = 0; j < 16; j++) Ws[tid + j * 256] = W[tid + j * 256];
    #pragma unroll
    for (int j = 0; j < 32; j++) {
        int idx = tid + j * 256;
        int r = idx >> 6, c = idx & 63;
        int gr = row0 + r;
        Hs[r * 65 + c] = (gr < N_NODES) ? in[(size_t)gr * 64 + c] : 0.0f;
    }
    __syncthreads();

    int r0 = (tid >> 3) * 4;        // 0,4,...,124
    int c0 = (tid & 7) * 8;         // 0,8,...,56
    float acc[4][8];
    #pragma unroll
    for (int i = 0; i < 4; i++)
        #pragma unroll
        for (int j = 0; j < 8; j++) acc[i][j] = 0.0f;

    #pragma unroll
    for (int k = 0; k < 64; k++) {
        float4 w0 = *(const float4*)&Ws[k * 64 + c0];
        float4 w1 = *(const float4*)&Ws[k * 64 + c0 + 4];
        float a0 = Hs[(r0 + 0) * 65 + k];
        float a1 = Hs[(r0 + 1) * 65 + k];
        float a2 = Hs[(r0 + 2) * 65 + k];
        float a3 = Hs[(r0 + 3) * 65 + k];
        acc[0][0] += a0 * w0.x; acc[0][1] += a0 * w0.y; acc[0][2] += a0 * w0.z; acc[0][3] += a0 * w0.w;
        acc[0][4] += a0 * w1.x; acc[0][5] += a0 * w1.y; acc[0][6] += a0 * w1.z; acc[0][7] += a0 * w1.w;
        acc[1][0] += a1 * w0.x; acc[1][1] += a1 * w0.y; acc[1][2] += a1 * w0.z; acc[1][3] += a1 * w0.w;
        acc[1][4] += a1 * w1.x; acc[1][5] += a1 * w1.y; acc[1][6] += a1 * w1.z; acc[1][7] += a1 * w1.w;
        acc[2][0] += a2 * w0.x; acc[2][1] += a2 * w0.y; acc[2][2] += a2 * w0.z; acc[2][3] += a2 * w0.w;
        acc[2][4] += a2 * w1.x; acc[2][5] += a2 * w1.y; acc[2][6] += a2 * w1.z; acc[2][7] += a2 * w1.w;
        acc[3][0] += a3 * w0.x; acc[3][1] += a3 * w0.y; acc[3][2] += a3 * w0.z; acc[3][3] += a3 * w0.w;
        acc[3][4] += a3 * w1.x; acc[3][5] += a3 * w1.y; acc[3][6] += a3 * w1.z; acc[3][7] += a3 * w1.w;
    }

    #pragma unroll
    for (int i = 0; i < 4; i++) {
        int gr = row0 + r0 + i;
        if (gr < N_NODES) {
            float* dst = out + (size_t)gr * 64 + c0;
            *(float4*)dst       = make_float4(acc[i][0], acc[i][1], acc[i][2], acc[i][3]);
            *(float4*)(dst + 4) = make_float4(acc[i][4], acc[i][5], acc[i][6], acc[i][7]);
        }
    }
}

// layer 1: read external input x, write g_A
__global__ void k_gemm_x(const float* __restrict__ x, const float* __restrict__ W) {
    gemm_body(x, W, g_A);
}
// layers 2/3: read g_B, write g_A
__global__ void k_gemm_B(const float* __restrict__ W) {
    gemm_body(g_B, W, g_A);
}

// ---------------- aggregation: 2 nodes per warp, float4 per lane --------------
// reads g_A + g_edge, writes g_B.
__global__ void k_agg(const float* __restrict__ b, int do_relu) {
    int gtid = blockIdx.x * blockDim.x + threadIdx.x;
    int warp = gtid >> 5;
    int lane = threadIdx.x & 31;
    int node = warp * 2 + (lane >> 4);      // half-warp per node
    int sub  = lane & 15;
    if (node >= N_NODES) return;
    const float* __restrict__ hw = g_A;
    int f = sub * 4;

    float dv = g_dinv[node];
    int lo = g_off[node];
    int hi = g_off[node + 1];

    float4 acc = make_float4(0.f, 0.f, 0.f, 0.f);
    int e = lo;
    for (; e + 1 < hi; e += 2) {
        int2 e0 = g_edge[e];
        int2 e1 = g_edge[e + 1];
        float w0 = __int_as_float(e0.y);
        float w1 = __int_as_float(e1.y);
        float4 v0 = *(const float4*)&hw[(size_t)e0.x * 64 + f];
        float4 v1 = *(const float4*)&hw[(size_t)e1.x * 64 + f];
        acc.x += w0 * v0.x + w1 * v1.x;
        acc.y += w0 * v0.y + w1 * v1.y;
        acc.z += w0 * v0.z + w1 * v1.z;
        acc.w += w0 * v0.w + w1 * v1.w;
    }
    if (e < hi) {
        int2 e0 = g_edge[e];
        float w0 = __int_as_float(e0.y);
        float4 v0 = *(const float4*)&hw[(size_t)e0.x * 64 + f];
        acc.x += w0 * v0.x;
        acc.y += w0 * v0.y;
        acc.z += w0 * v0.z;
        acc.w += w0 * v0.w;
    }

    float4 self = *(const float4*)&hw[(size_t)node * 64 + f];
    float4 bb   = *(const float4*)&b[f];
    float dv2 = dv * dv;
    float ox = dv * acc.x + dv2 * self.x + bb.x;
    float oy = dv * acc.y + dv2 * self.y + bb.y;
    float oz = dv * acc.z + dv2 * self.z + bb.z;
    float ow = dv * acc.w + dv2 * self.w + bb.w;
    if (do_relu) {
        ox = fmaxf(ox, 0.f); oy = fmaxf(oy, 0.f);
        oz = fmaxf(oz, 0.f); ow = fmaxf(ow, 0.f);
    }
    *(float4*)&g_B[(size_t)node * 64 + f] = make_float4(ox, oy, oz, ow);
}

// ---------------- pool: one block (64 threads) per graph ----------------------
__device__ __forceinline__ int lb_i32(const int* a, int n, int key) {
    int lo = 0, hi = n;
    while (lo < hi) {
        int mid = (lo + hi) >> 1;
        if (a[mid] < key) lo = mid + 1; else hi = mid;
    }
    return lo;
}

__global__ void k_pool(const int* __restrict__ batch) {
    int g = blockIdx.x;
    int f = threadIdx.x;   // 0..63
    int lo = lb_i32(batch, N_NODES, g);
    int hi = lb_i32(batch, N_NODES, g + 1);
    float s = 0.f;
    for (int n = lo; n < hi; n++) s += g_B[(size_t)n * 64 + f];
    int cnt = hi - lo;
    float denom = (float)max(cnt, 1);
    g_pooled[g * 64 + f] = s / denom;
}

// ---------------- dense + softmax + threshold: 4 graphs per block -------------
__device__ __forceinline__ void softmax_emit(float* l, float* red, int tid,
                                             float* orow) {
    float mx = l[0];
    #pragma unroll
    for (int j = 1; j < 8; j++) mx = fmaxf(mx, l[j]);
    red[tid] = mx;
    __syncthreads();
    for (int s = 128; s > 0; s >>= 1) {
        if (tid < s) red[tid] = fmaxf(red[tid], red[tid + s]);
        __syncthreads();
    }
    mx = red[0];
    __syncthreads();

    float ex[8];
    float se = 0.f;
    #pragma unroll
    for (int j = 0; j < 8; j++) { ex[j] = expf(l[j] - mx); se += ex[j]; }
    red[tid] = se;
    __syncthreads();
    for (int s = 128; s > 0; s >>= 1) {
        if (tid < s) red[tid] += red[tid + s];
        __syncthreads();
    }
    float total = red[0];
    __syncthreads();   // red free for next use

    #pragma unroll
    for (int j = 0; j < 8; j++)
        orow[tid + j * 256] = (ex[j] >= 0.5f * total) ? 1.0f : 0.0f;
}

__global__ void k_dense4(const float* __restrict__ Wd,
                         const float* __restrict__ bd,
                         float* __restrict__ out) {
    __shared__ float p[4][64];
    __shared__ float red[256];
    int tid = threadIdx.x;           // 256 threads
    int g0  = blockIdx.x * 4;        // 256 blocks * 4 graphs

    {
        int g = tid >> 6, f = tid & 63;
        p[g][f] = g_pooled[(g0 + g) * 64 + f];
    }
    __syncthreads();

    float l0[8], l1[8], l2[8], l3[8];
    #pragma unroll
    for (int j = 0; j < 8; j++) {
        float bv = bd[tid + j * 256];
        l0[j] = bv; l1[j] = bv; l2[j] = bv; l3[j] = bv;
    }
    for (int k = 0; k < 64; k++) {
        const float* wrow = Wd + (size_t)k * BIO;
        float w[8];
        #pragma unroll
        for (int j = 0; j < 8; j++) w[j] = wrow[tid + j * 256];
        float p0 = p[0][k], p1 = p[1][k], p2 = p[2][k], p3 = p[3][k];
        #pragma unroll
        for (int j = 0; j < 8; j++) {
            l0[j] += p0 * w[j];
            l1[j] += p1 * w[j];
            l2[j] += p2 * w[j];
            l3[j] += p3 * w[j];
        }
    }

    softmax_emit(l0, red, tid, out + (size_t)(g0 + 0) * BIO);
    softmax_emit(l1, red, tid, out + (size_t)(g0 + 1) * BIO);
    softmax_emit(l2, red, tid, out + (size_t)(g0 + 2) * BIO);
    softmax_emit(l3, red, tid, out + (size_t)(g0 + 3) * BIO);
}

// ---------------- launch ------------------------------------------------------
extern "C" void kernel_launch(void* const* d_in, const int* in_sizes, int n_in,
                              void* d_out, int out_size) {
    // Identify inputs by element count (robust to metadata ordering).
    const float *x = 0, *W1 = 0, *b1 = 0, *W2 = 0, *b2 = 0, *W3 = 0, *b3 = 0,
                *Wd = 0, *bd = 0;
    const int *ei = 0, *batch = 0;
    int nW = 0, nb = 0;
    for (int i = 0; i < n_in; i++) {
        int sz = in_sizes[i];
        if      (sz == N_NODES * F)   x     = (const float*)d_in[i];
        else if (sz == 2 * N_EDGES)   ei    = (const int*)d_in[i];
        else if (sz == N_NODES)       batch = (const int*)d_in[i];
        else if (sz == F * F) {
            if      (nW == 0) W1 = (const float*)d_in[i];
            else if (nW == 1) W2 = (const float*)d_in[i];
            else              W3 = (const float*)d_in[i];
            nW++;
        }
        else if (sz == F) {
            if      (nb == 0) b1 = (const float*)d_in[i];
            else if (nb == 1) b2 = (const float*)d_in[i];
            else              b3 = (const float*)d_in[i];
            nb++;
        }
        else if (sz == F * BIO)       Wd = (const float*)d_in[i];
        else if (sz == BIO)           bd = (const float*)d_in[i];
    }
    float* out = (float*)d_out;

    k_zero_deg<<<(N_NODES + 255) / 256, 256>>>();
    k_hist<<<(N_EDGES + 255) / 256, 256>>>(ei);
    k_dinv<<<(N_NODES + 255) / 256, 256>>>();
    k_scan_partial<<<SCAN_NB, 256>>>();
    k_scan_blocks<<<1, 512>>>();
    k_scan_offsets<<<SCAN_NB, 256>>>();
    k_fill<<<(N_EDGES + 255) / 256, 256>>>(ei);

    // layer 1
    k_gemm_x<<<GEMM_NB, 256>>>(x, W1);
    k_agg<<<6250, 256>>>(b1, 1);
    // layer 2
    k_gemm_B<<<GEMM_NB, 256>>>(W2);
    k_agg<<<6250, 256>>>(b2, 1);
    // layer 3
    k_gemm_B<<<GEMM_NB, 256>>>(W3);
    k_agg<<<6250, 256>>>(b3, 0);

    k_pool<<<N_GRAPHS, 64>>>(batch);
    k_dense4<<<N_GRAPHS / 4, 256>>>(Wd, bd, out);
}